// round 15
// baseline (speedup 1.0000x reference)
#include <cuda_runtime.h>
#include <cuda_bf16.h>
#include <cuda_fp16.h>
#include <math.h>
#include <cstdint>

#define NN 4096
#define DD 128
#define HH 4
#define NMID 9
#define PSTR 40   // gemm: 16-bit elems per smem row (80B)
#define PSTR2 72  // attn: 16-bit elems per smem row (144B, 64-k chunks)

typedef unsigned long long u64;

// Wt (split weights) layout offsets, in elements
#define WT_OFF0 0
#define WT_OFFM(l) (65536 + (size_t)(l) * 262144)
#define WT_OFFO 2424832
#define WT_TOTAL 2490368

// ===========================================================================
// PTX helpers (sm_80-class: compiles for plain sm_103)
// ===========================================================================
__device__ __forceinline__ uint32_t smem_u32(const void* p) {
    uint32_t a;
    asm("{ .reg .u64 t; cvta.to.shared.u64 t, %1; cvt.u32.u64 %0, t; }" : "=r"(a) : "l"(p));
    return a;
}
__device__ __forceinline__ void ldsm_x4(unsigned* r, uint32_t addr) {
    asm volatile("ldmatrix.sync.aligned.m8n8.x4.shared.b16 {%0,%1,%2,%3}, [%4];"
                 : "=r"(r[0]), "=r"(r[1]), "=r"(r[2]), "=r"(r[3]) : "r"(addr));
}
__device__ __forceinline__ void mma_bf16(float* d, const unsigned* a, const unsigned* b) {
    asm volatile(
        "mma.sync.aligned.m16n8k16.row.col.f32.bf16.bf16.f32 "
        "{%0,%1,%2,%3}, {%4,%5,%6,%7}, {%8,%9}, {%0,%1,%2,%3};"
        : "+f"(d[0]), "+f"(d[1]), "+f"(d[2]), "+f"(d[3])
        : "r"(a[0]), "r"(a[1]), "r"(a[2]), "r"(a[3]), "r"(b[0]), "r"(b[1]));
}
__device__ __forceinline__ void mma_f16(float* d, const unsigned* a, const unsigned* b) {
    asm volatile(
        "mma.sync.aligned.m16n8k16.row.col.f32.f16.f16.f32 "
        "{%0,%1,%2,%3}, {%4,%5,%6,%7}, {%8,%9}, {%0,%1,%2,%3};"
        : "+f"(d[0]), "+f"(d[1]), "+f"(d[2]), "+f"(d[3])
        : "r"(a[0]), "r"(a[1]), "r"(a[2]), "r"(a[3]), "r"(b[0]), "r"(b[1]));
}
__device__ __forceinline__ void cp16(uint32_t dst, const void* src) {
    asm volatile("cp.async.ca.shared.global [%0], [%1], 16;" :: "r"(dst), "l"(src) : "memory");
}
#define CP_COMMIT() asm volatile("cp.async.commit_group;" ::: "memory")
#define CP_WAIT0()  asm volatile("cp.async.wait_group 0;" ::: "memory")
#define CP_WAIT1()  asm volatile("cp.async.wait_group 1;" ::: "memory")

// ===========================================================================
// Scratch (device globals)
// ===========================================================================
__device__ __align__(16) __half g_WhT[HH * DD * NN];   // [h][n=128][k=4096] fp16
__device__ __align__(16) __nv_bfloat16 g_Xhi[NN * 512];
__device__ __align__(16) __nv_bfloat16 g_Xlo[NN * 512];
__device__ __align__(16) __nv_bfloat16 g_Wt_hi[WT_TOTAL];
__device__ __align__(16) __nv_bfloat16 g_Wt_lo[WT_TOTAL];
__device__ float g_f1[HH * NN];
__device__ float g_fmaxp[HH * 64];   // per-CTA f2 max partials
__device__ __align__(16) float g_colB[HH * NN];
__device__ __align__(16) float g_colD[HH * NN];
__device__ unsigned g_mask[NN * 128];

// ===========================================================================
// adj > 0 -> bitmask
// ===========================================================================
__global__ void build_mask_kernel(const float* __restrict__ adj,
                                  unsigned* __restrict__ mask) {
    int i = blockIdx.x;
    int t = threadIdx.x;
    int lane = t & 31;
    const float* row = adj + (size_t)i * NN;
    for (int word = t >> 5; word < 128; word += 8) {
        float v = row[word * 32 + lane];
        unsigned b = __ballot_sync(0xffffffffu, v > 0.f);
        if (lane == 0) mask[i * 128 + word] = b;
    }
}

__global__ void hrc_kernel(const int* __restrict__ head, const int* __restrict__ rel,
                           const float* __restrict__ ee, const float* __restrict__ re,
                           float* __restrict__ out) {
    int i = blockIdx.x;
    int d = threadIdx.x;
    out[(size_t)i * 128 + d] =
        ee[(size_t)head[i] * 128 + d] + re[(size_t)rel[i] * 128 + d];
}

// ===========================================================================
// fp32 -> bf16 hi/lo split (flat) — layer-0 input (ee) only
// ===========================================================================
__global__ void split_kernel(const float* __restrict__ src,
                             __nv_bfloat16* __restrict__ hi,
                             __nv_bfloat16* __restrict__ lo, int n) {
    int i = blockIdx.x * 256 + threadIdx.x;
    if (i < n) {
        float v = src[i];
        __nv_bfloat16 h = __float2bfloat16(v);
        hi[i] = h;
        lo[i] = __float2bfloat16(v - __bfloat162float(h));
    }
}

// ===========================================================================
// ONE-SHOT weight transpose + bf16 split for ALL 11 layers. grid = 2432.
// ===========================================================================
__global__ void wsplit_all_kernel(const float* __restrict__ W0,
                                  const float* __restrict__ Wm,
                                  const float* __restrict__ Wo,
                                  __nv_bfloat16* __restrict__ dhi,
                                  __nv_bfloat16* __restrict__ dlo) {
    int b = blockIdx.x;
    const float* src;
    int kdim, kt, nt;
    size_t dst;
    if (b < 64) {
        int h = b >> 4, rem = b & 15;
        kt = rem >> 2; nt = rem & 3;
        src = W0 + (size_t)h * 128 * 128;
        kdim = 128;
        dst = WT_OFF0 + (size_t)h * 128 * 128;
    } else if (b < 2368) {
        int b2 = b - 64;
        int l = b2 >> 8, rem = b2 & 255;
        int h = rem >> 6, rem2 = rem & 63;
        kt = rem2 >> 2; nt = rem2 & 3;
        src = Wm + ((size_t)l * HH + h) * 512 * 128;
        kdim = 512;
        dst = WT_OFFM(l) + (size_t)h * 512 * 128;
    } else {
        int rem = b - 2368;
        kt = rem >> 2; nt = rem & 3;
        src = Wo;
        kdim = 512;
        dst = WT_OFFO;
    }
    int kbase = kt * 32, nbase = nt * 32;
    __shared__ float ts[32][33];
    int t = threadIdx.x;
#pragma unroll
    for (int l = 0; l < 4; l++) {
        int e = t + l * 256;
        int r = e >> 5, c = e & 31;
        ts[r][c] = src[(size_t)(kbase + r) * 128 + nbase + c];
    }
    __syncthreads();
#pragma unroll
    for (int l = 0; l < 4; l++) {
        int e = t + l * 256;
        int r = e >> 5, c = e & 31;
        float v = ts[c][r];
        __nv_bfloat16 hi = __float2bfloat16(v);
        __nv_bfloat16 lo = __float2bfloat16(v - __bfloat162float(hi));
        size_t o = dst + (size_t)(nbase + r) * kdim + kbase + c;
        dhi[o] = hi;
        dlo[o] = lo;
    }
}

// ===========================================================================
// FUSED GEMM (3-stage cp.async pipeline): Wh_tile = X @ W (3-pass bf16 split);
// epilogue: f1 + colB/colD + f2-max partial + transposed fp16 WhT write.
// smem: 3 x 30720 tile buffers; epilogue reuses [0,34336).
// ===========================================================================
#define GEMM_SMEM 92160

__global__ void __launch_bounds__(256)
gemm_fused_kernel(const __nv_bfloat16* __restrict__ Xhi, const __nv_bfloat16* __restrict__ Xlo,
                  const __nv_bfloat16* __restrict__ WtHi, const __nv_bfloat16* __restrict__ WtLo,
                  const float* __restrict__ Avec,
                  __half* __restrict__ WhT, float* __restrict__ f1g,
                  float* __restrict__ colB, float* __restrict__ colD,
                  float* __restrict__ fmaxp, int Fin) {
    extern __shared__ __align__(16) char smem[];
    uint32_t sb = smem_u32(smem);

    int h = blockIdx.y;
    int row0 = blockIdx.x * 64;
    int t = threadIdx.x, wid = t >> 5, lane = t & 31;
    int wr = wid & 3, wc = wid >> 2;
    const __nv_bfloat16* Wth = WtHi + (size_t)h * 128 * Fin;
    const __nv_bfloat16* Wtl = WtLo + (size_t)h * 128 * Fin;

    float d[8][4] = {};

    uint32_t a_off = (uint32_t)(wr * 16 + ((lane >> 3) & 1) * 8 + (lane & 7)) * (PSTR * 2)
                   + (uint32_t)((lane >> 4) * 8) * 2;
    uint32_t b_roff = (uint32_t)(wc * 64 + (lane >> 4) * 8 + (lane & 7)) * (PSTR * 2);
    uint32_t b_koff = (uint32_t)(((lane >> 3) & 1) * 8) * 2;

    auto stage = [&](int k0, int buf) {
        uint32_t base = sb + (uint32_t)buf * 30720;
        {
            int m = t >> 2, q = t & 3;
            size_t go = (size_t)(row0 + m) * Fin + k0 + q * 8;
            cp16(base + 0    + m * 80 + q * 16, Xhi + go);
            cp16(base + 5120 + m * 80 + q * 16, Xlo + go);
        }
#pragma unroll
        for (int l = 0; l < 2; l++) {
            int idx = t + l * 256;
            int n = idx >> 2, q = idx & 3;
            size_t go = (size_t)n * Fin + k0 + q * 8;
            cp16(base + 10240 + n * 80 + q * 16, Wth + go);
            cp16(base + 20480 + n * 80 + q * 16, Wtl + go);
        }
        CP_COMMIT();
    };

    int nIter = Fin >> 5;
    stage(0, 0);
    stage(32, 1);
    for (int it = 0; it < nIter; it++) {
        int buf = it % 3;
        if (it + 1 < nIter) CP_WAIT1(); else CP_WAIT0();   // tiles(it) arrived
        __syncthreads();     // publish tiles(it); readers of buf done last at it-1
        if (it + 2 < nIter) stage((it + 2) * 32, (it + 2) % 3);
        uint32_t base = sb + (uint32_t)buf * 30720;
        uint32_t sAhi = base, sAlo = base + 5120;
        uint32_t sBhi = base + 10240, sBlo = base + 20480;
#pragma unroll
        for (int s = 0; s < 2; s++) {
            unsigned ah[4], al[4];
            ldsm_x4(ah, sAhi + a_off + s * 32);
            ldsm_x4(al, sAlo + a_off + s * 32);
#pragma unroll
            for (int pp = 0; pp < 4; pp++) {
                unsigned bh[4], bl[4];
                uint32_t boff = b_roff + (uint32_t)(pp * 16) * (PSTR * 2) + b_koff + s * 32;
                ldsm_x4(bh, sBhi + boff);
                ldsm_x4(bl, sBlo + boff);
                mma_bf16(d[2 * pp],     ah, bh);
                mma_bf16(d[2 * pp + 1], ah, bh + 2);
                mma_bf16(d[2 * pp],     ah, bl);
                mma_bf16(d[2 * pp + 1], ah, bl + 2);
                mma_bf16(d[2 * pp],     al, bh);
                mma_bf16(d[2 * pp + 1], al, bh + 2);
            }
        }
    }

    // ------- fused epilogue -------
    __syncthreads();   // all ldsm reads done; smem re-purposed
    float* Ws = (float*)smem;              // [64][130]
    float* fr = (float*)(smem + 33280);    // [2][2][64]
    float* sc = (float*)(smem + 34304);    // [2] per-warp f2 maxes
    const float* av = Avec + h * 256;

    int rloc = wr * 16 + (lane >> 2);
    int cb = wc * 64 + (lane & 3) * 2;
    float s1a = 0.f, s2a = 0.f, s1b = 0.f, s2b = 0.f;
#pragma unroll
    for (int nt = 0; nt < 8; nt++) {
        int col = cb + nt * 8;
        float a1x = av[col], a1y = av[col + 1];
        float a2x = av[128 + col], a2y = av[128 + col + 1];
        float d0 = d[nt][0], d1 = d[nt][1], d2 = d[nt][2], d3 = d[nt][3];
        Ws[rloc * 130 + col] = d0;
        Ws[rloc * 130 + col + 1] = d1;
        Ws[(rloc + 8) * 130 + col] = d2;
        Ws[(rloc + 8) * 130 + col + 1] = d3;
        s1a += d0 * a1x + d1 * a1y;
        s2a += d0 * a2x + d1 * a2y;
        s1b += d2 * a1x + d3 * a1y;
        s2b += d2 * a2x + d3 * a2y;
    }
#pragma unroll
    for (int o = 1; o <= 2; o <<= 1) {
        s1a += __shfl_xor_sync(0xffffffffu, s1a, o);
        s2a += __shfl_xor_sync(0xffffffffu, s2a, o);
        s1b += __shfl_xor_sync(0xffffffffu, s1b, o);
        s2b += __shfl_xor_sync(0xffffffffu, s2b, o);
    }
    if ((lane & 3) == 0) {
        fr[(0 * 2 + wc) * 64 + rloc] = s1a;
        fr[(0 * 2 + wc) * 64 + rloc + 8] = s1b;
        fr[(1 * 2 + wc) * 64 + rloc] = s2a;
        fr[(1 * 2 + wc) * 64 + rloc + 8] = s2b;
    }
    __syncthreads();
    if (t < 64) {
        float v1 = fr[0 * 64 + t] + fr[1 * 64 + t];
        float v2 = fr[2 * 64 + t] + fr[3 * 64 + t];
        int idx = h * NN + row0 + t;
        f1g[idx] = v1;
        colB[idx] = __expf(v2);
        colD[idx] = __expf(0.2f * v2);
        float mm = v2;
#pragma unroll
        for (int o = 16; o; o >>= 1) mm = fmaxf(mm, __shfl_xor_sync(0xffffffffu, mm, o));
        if (lane == 0) sc[wid] = mm;
    }

    // transposed fp16 write (reads Ws; disjoint from fr/sc)
#pragma unroll
    for (int i = 0; i < 4; i++) {
        int n = t >> 1, kg = 4 * (t & 1) + i;
        __half hv[8];
#pragma unroll
        for (int j = 0; j < 8; j++)
            hv[j] = __float2half_rn(Ws[(kg * 8 + j) * 130 + n]);
        size_t o = (size_t)(h * 128 + n) * NN + row0 + kg * 8;
        *(uint4*)&WhT[o] = *(uint4*)hv;
    }
    __syncthreads();
    if (t == 0) fmaxp[h * 64 + blockIdx.x] = fmaxf(sc[0], sc[1]);
}

// ===========================================================================
// Pipelined mma.sync attention, single-pass fp16, 64-k chunks, 3-stage B
// pipeline (wait_group 1). CTA 64m x 128n, grid (64, H). smem (144B rows):
//   P[buf]: buf*9216 (2 bufs, 64 x 144B) = 18432
//   B[buf]: 18432 + buf*18432 (3 bufs, 128 x 144B) = 55296
//   rowsum: 73728 (64 floats) -> total 73984
// ===========================================================================
#define ATT_SMEM 73984

__global__ void __launch_bounds__(256)
attn_mma_kernel(const __half* __restrict__ WhT,
                const float* __restrict__ f1v, const float* __restrict__ fmaxp,
                const float* __restrict__ colB, const float* __restrict__ colD,
                const unsigned* __restrict__ mask,
                float* __restrict__ out, int out_stride,
                __nv_bfloat16* __restrict__ xhi, __nv_bfloat16* __restrict__ xlo) {
    extern __shared__ __align__(16) char smem[];
    uint32_t sb = smem_u32(smem);
    const uint32_t sP = sb;
    const uint32_t sB = sb + 18432;
    float* rsum = (float*)(smem + 73728);

    int h = blockIdx.y;
    int row0 = blockIdx.x * 64;
    int hbase = h * NN;
    int t = threadIdx.x, wid = t >> 5, lane = t & 31;
    int wr = wid & 3, wc = wid >> 2;

    const __half* Whh = WhT + (size_t)(h * 128) * NN;

    // per-head f2 max from 64 partials (all warps redundantly)
    float mF2 = fmaxf(fmaxp[h * 64 + lane], fmaxp[h * 64 + 32 + lane]);
#pragma unroll
    for (int o = 16; o; o >>= 1) mF2 = fmaxf(mF2, __shfl_xor_sync(0xffffffffu, mF2, o));

    // P-gen role: thread covers row pr (0..63), two k-octets kq0, kq0+1
    int pr = t >> 2, kq0 = (t & 3) * 2;
    float f1r = f1v[hbase + row0 + pr];
    float xm = f1r + mF2;
    float m = xm > 0.f ? xm : 0.2f * xm;
    float Ar = __expf(f1r - m);
    float Cr = __expf(0.2f * f1r - m);
    float psum = 0.f;

    const unsigned* mrow = mask + (size_t)(row0 + pr) * 128;
    const float* cBp = colB + hbase;
    const float* cDp = colD + hbase;

    uint32_t a_off = (uint32_t)(wr * 16 + ((lane >> 3) & 1) * 8 + (lane & 7)) * (PSTR2 * 2)
                   + (uint32_t)((lane >> 4) * 8) * 2;
    uint32_t b_roff = (uint32_t)(wc * 64 + (lane >> 4) * 8 + (lane & 7)) * (PSTR2 * 2);
    uint32_t b_koff = (uint32_t)(((lane >> 3) & 1) * 8) * 2;

    float d[8][4] = {};

    auto stage = [&](int c, int buf) {
#pragma unroll
        for (int l = 0; l < 4; l++) {
            int idx = t + l * 256;
            int n = idx >> 3, q = idx & 7;
            size_t go = (size_t)n * NN + c * 64 + q * 8;
            cp16(sB + (uint32_t)buf * 18432 + n * 144 + q * 16, Whh + go);
        }
        CP_COMMIT();
    };
    auto pgen = [&](int c, int buf) {
        unsigned wrd = mrow[2 * c + (kq0 >> 2)];
#pragma unroll
        for (int j2 = 0; j2 < 2; j2++) {
            int o = kq0 + j2;
            int kb = c * 64 + o * 8;
            unsigned w8 = wrd >> ((o & 3) * 8);
            float4 b0 = *(const float4*)(cBp + kb);
            float4 b1 = *(const float4*)(cBp + kb + 4);
            float4 d0 = *(const float4*)(cDp + kb);
            float4 d1 = *(const float4*)(cDp + kb + 4);
            float p[8];
            p[0] = (w8 & 1u)   ? fmaxf(Ar * b0.x, Cr * d0.x) : 0.f;
            p[1] = (w8 & 2u)   ? fmaxf(Ar * b0.y, Cr * d0.y) : 0.f;
            p[2] = (w8 & 4u)   ? fmaxf(Ar * b0.z, Cr * d0.z) : 0.f;
            p[3] = (w8 & 8u)   ? fmaxf(Ar * b0.w, Cr * d0.w) : 0.f;
            p[4] = (w8 & 16u)  ? fmaxf(Ar * b1.x, Cr * d1.x) : 0.f;
            p[5] = (w8 & 32u)  ? fmaxf(Ar * b1.y, Cr * d1.y) : 0.f;
            p[6] = (w8 & 64u)  ? fmaxf(Ar * b1.z, Cr * d1.z) : 0.f;
            p[7] = (w8 & 128u) ? fmaxf(Ar * b1.w, Cr * d1.w) : 0.f;
            psum += ((p[0] + p[1]) + (p[2] + p[3])) + ((p[4] + p[5]) + (p[6] + p[7]));
            uint4 u;
            unsigned* ph = &u.x;
#pragma unroll
            for (int j = 0; j < 4; j++) {
                __half2 h2 = __floats2half2_rn(p[2 * j], p[2 * j + 1]);
                ph[j] = *(unsigned*)&h2;
            }
            *(uint4*)(smem + buf * 9216 + pr * 144 + o * 16) = u;
        }
    };

    stage(0, 0);
    stage(1, 1);
    pgen(0, 0);

    for (int c = 0; c < 64; c++) {
        int bufB = c % 3;
        int bufP = c & 1;
        if (c + 1 < 64) CP_WAIT1(); else CP_WAIT0();   // B(c) arrived
        __syncthreads();     // publish B(c), P(c); readers of reused bufs done
        if (c + 2 < 64) stage(c + 2, (c + 2) % 3);     // overlaps mma below
        uint32_t pH = sP + (uint32_t)bufP * 9216;
        uint32_t bH = sB + (uint32_t)bufB * 18432;
#pragma unroll
        for (int s = 0; s < 4; s++) {
            unsigned ah[4];
            ldsm_x4(ah, pH + a_off + s * 32);
#pragma unroll
            for (int pp = 0; pp < 4; pp++) {
                unsigned bh[4];
                uint32_t boff = b_roff + (uint32_t)(pp * 16) * (PSTR2 * 2) + b_koff + s * 32;
                ldsm_x4(bh, bH + boff);
                mma_f16(d[2 * pp],     ah, bh);
                mma_f16(d[2 * pp + 1], ah, bh + 2);
            }
        }
        if (c + 1 < 64) pgen(c + 1, bufP ^ 1);   // fills tensor-pipe drain window
    }

    psum += __shfl_xor_sync(0xffffffffu, psum, 1);
    psum += __shfl_xor_sync(0xffffffffu, psum, 2);
    if ((t & 3) == 0) rsum[pr] = psum;
    __syncthreads();

    int rloc = wr * 16 + (lane >> 2);
    float inv0 = 1.f / rsum[rloc];
    float inv1 = 1.f / rsum[rloc + 8];
    int r0 = row0 + rloc;
    int cbase = h * 128 + wc * 64 + (lane & 3) * 2;
#pragma unroll
    for (int nt = 0; nt < 8; nt++) {
        int col = cbase + nt * 8;
        float v0 = d[nt][0] * inv0, v1 = d[nt][1] * inv0;
        float v2 = d[nt][2] * inv1, v3 = d[nt][3] * inv1;
        v0 = v0 > 0.f ? v0 : expm1f(v0);
        v1 = v1 > 0.f ? v1 : expm1f(v1);
        v2 = v2 > 0.f ? v2 : expm1f(v2);
        v3 = v3 > 0.f ? v3 : expm1f(v3);
        if (xhi) {
            __nv_bfloat16 h0 = __float2bfloat16(v0), h1 = __float2bfloat16(v1);
            __nv_bfloat16 h2 = __float2bfloat16(v2), h3 = __float2bfloat16(v3);
            __nv_bfloat16 l0 = __float2bfloat16(v0 - __bfloat162float(h0));
            __nv_bfloat16 l1 = __float2bfloat16(v1 - __bfloat162float(h1));
            __nv_bfloat16 l2 = __float2bfloat16(v2 - __bfloat162float(h2));
            __nv_bfloat16 l3 = __float2bfloat16(v3 - __bfloat162float(h3));
            *(__nv_bfloat162*)&xhi[(size_t)r0 * 512 + col] = __nv_bfloat162(h0, h1);
            *(__nv_bfloat162*)&xlo[(size_t)r0 * 512 + col] = __nv_bfloat162(l0, l1);
            *(__nv_bfloat162*)&xhi[(size_t)(r0 + 8) * 512 + col] = __nv_bfloat162(h2, h3);
            *(__nv_bfloat162*)&xlo[(size_t)(r0 + 8) * 512 + col] = __nv_bfloat162(l2, l3);
        } else {
            *(float2*)&out[(size_t)r0 * out_stride + col] = make_float2(v0, v1);
            *(float2*)&out[(size_t)(r0 + 8) * out_stride + col] = make_float2(v2, v3);
        }
    }
}

// ===========================================================================
extern "C" void kernel_launch(void* const* d_in, const int* in_sizes, int n_in,
                              void* d_out, int out_size) {
    const int* head = (const int*)d_in[0];
    const int* rel = (const int*)d_in[1];
    const float* adj = (const float*)d_in[2];
    const float* ee = (const float*)d_in[3];
    const float* re = (const float*)d_in[4];
    const float* W0 = (const float*)d_in[5];
    const float* a0 = (const float*)d_in[6];
    const float* Wm = (const float*)d_in[7];
    const float* am = (const float*)d_in[8];
    const float* Wo = (const float*)d_in[9];
    const float* ao = (const float*)d_in[10];
    float* out = (float*)d_out;

    float *f1, *fmaxp, *cB, *cD;
    __half* WhT;
    __nv_bfloat16 *Xhi, *Xlo, *Wth, *Wtl;
    unsigned* mask;
    cudaGetSymbolAddress((void**)&f1, g_f1);
    cudaGetSymbolAddress((void**)&fmaxp, g_fmaxp);
    cudaGetSymbolAddress((void**)&cB, g_colB);
    cudaGetSymbolAddress((void**)&cD, g_colD);
    cudaGetSymbolAddress((void**)&WhT, g_WhT);
    cudaGetSymbolAddress((void**)&Xhi, g_Xhi);
    cudaGetSymbolAddress((void**)&Xlo, g_Xlo);
    cudaGetSymbolAddress((void**)&Wth, g_Wt_hi);
    cudaGetSymbolAddress((void**)&Wtl, g_Wt_lo);
    cudaGetSymbolAddress((void**)&mask, g_mask);

    cudaFuncSetAttribute(attn_mma_kernel, cudaFuncAttributeMaxDynamicSharedMemorySize, ATT_SMEM);
    cudaFuncSetAttribute(gemm_fused_kernel, cudaFuncAttributeMaxDynamicSharedMemorySize, GEMM_SMEM);

    build_mask_kernel<<<NN, 256>>>(adj, mask);
    hrc_kernel<<<NN, 128>>>(head, rel, ee, re, out + (size_t)NN * 128);
    split_kernel<<<(NN * 128 + 255) / 256, 256>>>(ee, Xhi, Xlo, NN * 128);
    wsplit_all_kernel<<<2432, 256>>>(W0, Wm, Wo, Wth, Wtl);

    // ---- layer 0: Fin = 128 ----
    gemm_fused_kernel<<<dim3(64, HH), 256, GEMM_SMEM>>>(Xhi, Xlo, Wth + WT_OFF0, Wtl + WT_OFF0,
                                                        a0, WhT, f1, cB, cD, fmaxp, 128);
    attn_mma_kernel<<<dim3(64, HH), 256, ATT_SMEM>>>(WhT, f1, fmaxp, cB, cD, mask,
                                                     nullptr, 0, Xhi, Xlo);

    // ---- 9 middle layers: Fin = 512 ----
    for (int l = 0; l < NMID; l++) {
        gemm_fused_kernel<<<dim3(64, HH), 256, GEMM_SMEM>>>(Xhi, Xlo,
                                                            Wth + WT_OFFM(l), Wtl + WT_OFFM(l),
                                                            am + (size_t)l * HH * 256,
                                                            WhT, f1, cB, cD, fmaxp, 512);
        attn_mma_kernel<<<dim3(64, HH), 256, ATT_SMEM>>>(WhT, f1, fmaxp, cB, cD, mask,
                                                         nullptr, 0, Xhi, Xlo);
    }

    // ---- output layer: 1 head, Fin = 512 ----
    gemm_fused_kernel<<<dim3(64, 1), 256, GEMM_SMEM>>>(Xhi, Xlo, Wth + WT_OFFO, Wtl + WT_OFFO,
                                                       ao, WhT, f1, cB, cD, fmaxp, 512);
    attn_mma_kernel<<<dim3(64, 1), 256, ATT_SMEM>>>(WhT, f1, fmaxp, cB, cD, mask,
                                                    out, 128, nullptr, nullptr);
}

// round 16
// speedup vs baseline: 1.0016x; 1.0016x over previous
#include <cuda_runtime.h>
#include <cuda_bf16.h>
#include <cuda_fp16.h>
#include <math.h>
#include <cstdint>

#define NN 4096
#define DD 128
#define HH 4
#define NMID 9
#define PSTR 40   // gemm: 16-bit elems per smem row (80B)
#define PSTR2 72  // attn: 16-bit elems per smem row (144B, 64-k chunks)

typedef unsigned long long u64;

// Wt (split weights) layout offsets, in elements
#define WT_OFF0 0
#define WT_OFFM(l) (65536 + (size_t)(l) * 262144)
#define WT_OFFO 2424832
#define WT_TOTAL 2490368

// ===========================================================================
// PTX helpers (sm_80-class: compiles for plain sm_103)
// ===========================================================================
__device__ __forceinline__ uint32_t smem_u32(const void* p) {
    uint32_t a;
    asm("{ .reg .u64 t; cvta.to.shared.u64 t, %1; cvt.u32.u64 %0, t; }" : "=r"(a) : "l"(p));
    return a;
}
__device__ __forceinline__ void ldsm_x4(unsigned* r, uint32_t addr) {
    asm volatile("ldmatrix.sync.aligned.m8n8.x4.shared.b16 {%0,%1,%2,%3}, [%4];"
                 : "=r"(r[0]), "=r"(r[1]), "=r"(r[2]), "=r"(r[3]) : "r"(addr));
}
__device__ __forceinline__ void mma_bf16(float* d, const unsigned* a, const unsigned* b) {
    asm volatile(
        "mma.sync.aligned.m16n8k16.row.col.f32.bf16.bf16.f32 "
        "{%0,%1,%2,%3}, {%4,%5,%6,%7}, {%8,%9}, {%0,%1,%2,%3};"
        : "+f"(d[0]), "+f"(d[1]), "+f"(d[2]), "+f"(d[3])
        : "r"(a[0]), "r"(a[1]), "r"(a[2]), "r"(a[3]), "r"(b[0]), "r"(b[1]));
}
__device__ __forceinline__ void mma_f16(float* d, const unsigned* a, const unsigned* b) {
    asm volatile(
        "mma.sync.aligned.m16n8k16.row.col.f32.f16.f16.f32 "
        "{%0,%1,%2,%3}, {%4,%5,%6,%7}, {%8,%9}, {%0,%1,%2,%3};"
        : "+f"(d[0]), "+f"(d[1]), "+f"(d[2]), "+f"(d[3])
        : "r"(a[0]), "r"(a[1]), "r"(a[2]), "r"(a[3]), "r"(b[0]), "r"(b[1]));
}
__device__ __forceinline__ void cp16(uint32_t dst, const void* src) {
    asm volatile("cp.async.cg.shared.global [%0], [%1], 16;" :: "r"(dst), "l"(src) : "memory");
}
#define CP_COMMIT() asm volatile("cp.async.commit_group;" ::: "memory")
#define CP_WAIT0()  asm volatile("cp.async.wait_group 0;" ::: "memory")

// ===========================================================================
// Scratch (device globals)
// ===========================================================================
__device__ __align__(16) __half g_WhT[HH * DD * NN];   // [h][n=128][k=4096] fp16
__device__ __align__(16) __nv_bfloat16 g_Xhi[NN * 512];
__device__ __align__(16) __nv_bfloat16 g_Xlo[NN * 512];
__device__ __align__(16) __nv_bfloat16 g_Wt_hi[WT_TOTAL];
__device__ __align__(16) __nv_bfloat16 g_Wt_lo[WT_TOTAL];
__device__ float g_f1[HH * NN];
__device__ float g_fmaxp[HH * 64];   // per-CTA f2 max partials
__device__ __align__(16) float g_colB[HH * NN];
__device__ __align__(16) float g_colD[HH * NN];
__device__ unsigned g_mask[NN * 128];

// ===========================================================================
// adj > 0 -> bitmask
// ===========================================================================
__global__ void build_mask_kernel(const float* __restrict__ adj,
                                  unsigned* __restrict__ mask) {
    int i = blockIdx.x;
    int t = threadIdx.x;
    int lane = t & 31;
    const float* row = adj + (size_t)i * NN;
    for (int word = t >> 5; word < 128; word += 8) {
        float v = row[word * 32 + lane];
        unsigned b = __ballot_sync(0xffffffffu, v > 0.f);
        if (lane == 0) mask[i * 128 + word] = b;
    }
}

__global__ void hrc_kernel(const int* __restrict__ head, const int* __restrict__ rel,
                           const float* __restrict__ ee, const float* __restrict__ re,
                           float* __restrict__ out) {
    int i = blockIdx.x;
    int d = threadIdx.x;
    out[(size_t)i * 128 + d] =
        ee[(size_t)head[i] * 128 + d] + re[(size_t)rel[i] * 128 + d];
}

// ===========================================================================
// fp32 -> bf16 hi/lo split (flat) — layer-0 input (ee) only
// ===========================================================================
__global__ void split_kernel(const float* __restrict__ src,
                             __nv_bfloat16* __restrict__ hi,
                             __nv_bfloat16* __restrict__ lo, int n) {
    int i = blockIdx.x * 256 + threadIdx.x;
    if (i < n) {
        float v = src[i];
        __nv_bfloat16 h = __float2bfloat16(v);
        hi[i] = h;
        lo[i] = __float2bfloat16(v - __bfloat162float(h));
    }
}

// ===========================================================================
// ONE-SHOT weight transpose + bf16 split for ALL 11 layers. grid = 2432.
// ===========================================================================
__global__ void wsplit_all_kernel(const float* __restrict__ W0,
                                  const float* __restrict__ Wm,
                                  const float* __restrict__ Wo,
                                  __nv_bfloat16* __restrict__ dhi,
                                  __nv_bfloat16* __restrict__ dlo) {
    int b = blockIdx.x;
    const float* src;
    int kdim, kt, nt;
    size_t dst;
    if (b < 64) {
        int h = b >> 4, rem = b & 15;
        kt = rem >> 2; nt = rem & 3;
        src = W0 + (size_t)h * 128 * 128;
        kdim = 128;
        dst = WT_OFF0 + (size_t)h * 128 * 128;
    } else if (b < 2368) {
        int b2 = b - 64;
        int l = b2 >> 8, rem = b2 & 255;
        int h = rem >> 6, rem2 = rem & 63;
        kt = rem2 >> 2; nt = rem2 & 3;
        src = Wm + ((size_t)l * HH + h) * 512 * 128;
        kdim = 512;
        dst = WT_OFFM(l) + (size_t)h * 512 * 128;
    } else {
        int rem = b - 2368;
        kt = rem >> 2; nt = rem & 3;
        src = Wo;
        kdim = 512;
        dst = WT_OFFO;
    }
    int kbase = kt * 32, nbase = nt * 32;
    __shared__ float ts[32][33];
    int t = threadIdx.x;
#pragma unroll
    for (int l = 0; l < 4; l++) {
        int e = t + l * 256;
        int r = e >> 5, c = e & 31;
        ts[r][c] = src[(size_t)(kbase + r) * 128 + nbase + c];
    }
    __syncthreads();
#pragma unroll
    for (int l = 0; l < 4; l++) {
        int e = t + l * 256;
        int r = e >> 5, c = e & 31;
        float v = ts[c][r];
        __nv_bfloat16 hi = __float2bfloat16(v);
        __nv_bfloat16 lo = __float2bfloat16(v - __bfloat162float(hi));
        size_t o = dst + (size_t)(nbase + r) * kdim + kbase + c;
        dhi[o] = hi;
        dlo[o] = lo;
    }
}

// ===========================================================================
// FUSED GEMM (cp.async double-buffered): Wh_tile = X @ W (3-pass bf16 split);
// epilogue: f1 + colB/colD + f2-max partial + transposed fp16 WhT write.
// smem: buf0 [0,30720), buf1 [30720,61440); epilogue reuses [0,34336).
// ===========================================================================
#define GEMM_SMEM 61440

__global__ void __launch_bounds__(256, 2)
gemm_fused_kernel(const __nv_bfloat16* __restrict__ Xhi, const __nv_bfloat16* __restrict__ Xlo,
                  const __nv_bfloat16* __restrict__ WtHi, const __nv_bfloat16* __restrict__ WtLo,
                  const float* __restrict__ Avec,
                  __half* __restrict__ WhT, float* __restrict__ f1g,
                  float* __restrict__ colB, float* __restrict__ colD,
                  float* __restrict__ fmaxp, int Fin) {
    extern __shared__ __align__(16) char smem[];
    uint32_t sb = smem_u32(smem);

    int h = blockIdx.y;
    int row0 = blockIdx.x * 64;
    int t = threadIdx.x, wid = t >> 5, lane = t & 31;
    int wr = wid & 3, wc = wid >> 2;
    const __nv_bfloat16* Wth = WtHi + (size_t)h * 128 * Fin;
    const __nv_bfloat16* Wtl = WtLo + (size_t)h * 128 * Fin;

    float d[8][4] = {};

    uint32_t a_off = (uint32_t)(wr * 16 + ((lane >> 3) & 1) * 8 + (lane & 7)) * (PSTR * 2)
                   + (uint32_t)((lane >> 4) * 8) * 2;
    uint32_t b_roff = (uint32_t)(wc * 64 + (lane >> 4) * 8 + (lane & 7)) * (PSTR * 2);
    uint32_t b_koff = (uint32_t)(((lane >> 3) & 1) * 8) * 2;

    auto stage = [&](int k0, int buf) {
        uint32_t base = sb + (uint32_t)buf * 30720;
        {
            int m = t >> 2, q = t & 3;
            size_t go = (size_t)(row0 + m) * Fin + k0 + q * 8;
            cp16(base + 0    + m * 80 + q * 16, Xhi + go);
            cp16(base + 5120 + m * 80 + q * 16, Xlo + go);
        }
#pragma unroll
        for (int l = 0; l < 2; l++) {
            int idx = t + l * 256;
            int n = idx >> 2, q = idx & 3;
            size_t go = (size_t)n * Fin + k0 + q * 8;
            cp16(base + 10240 + n * 80 + q * 16, Wth + go);
            cp16(base + 20480 + n * 80 + q * 16, Wtl + go);
        }
        CP_COMMIT();
    };

    int nIter = Fin >> 5;
    stage(0, 0);
    for (int it = 0; it < nIter; it++) {
        int buf = it & 1;
        CP_WAIT0();
        __syncthreads();     // publish tiles(it); readers of buf^1 done
        if (it + 1 < nIter) stage((it + 1) * 32, buf ^ 1);
        uint32_t base = sb + (uint32_t)buf * 30720;
        uint32_t sAhi = base, sAlo = base + 5120;
        uint32_t sBhi = base + 10240, sBlo = base + 20480;
#pragma unroll
        for (int s = 0; s < 2; s++) {
            unsigned ah[4], al[4];
            ldsm_x4(ah, sAhi + a_off + s * 32);
            ldsm_x4(al, sAlo + a_off + s * 32);
#pragma unroll
            for (int pp = 0; pp < 4; pp++) {
                unsigned bh[4], bl[4];
                uint32_t boff = b_roff + (uint32_t)(pp * 16) * (PSTR * 2) + b_koff + s * 32;
                ldsm_x4(bh, sBhi + boff);
                ldsm_x4(bl, sBlo + boff);
                mma_bf16(d[2 * pp],     ah, bh);
                mma_bf16(d[2 * pp + 1], ah, bh + 2);
                mma_bf16(d[2 * pp],     ah, bl);
                mma_bf16(d[2 * pp + 1], ah, bl + 2);
                mma_bf16(d[2 * pp],     al, bh);
                mma_bf16(d[2 * pp + 1], al, bh + 2);
            }
        }
    }

    // ------- fused epilogue -------
    __syncthreads();   // all ldsm reads done; smem re-purposed
    float* Ws = (float*)smem;              // [64][130]
    float* fr = (float*)(smem + 33280);    // [2][2][64]
    float* sc = (float*)(smem + 34304);    // [2] per-warp f2 maxes
    const float* av = Avec + h * 256;

    int rloc = wr * 16 + (lane >> 2);
    int cb = wc * 64 + (lane & 3) * 2;
    float s1a = 0.f, s2a = 0.f, s1b = 0.f, s2b = 0.f;
#pragma unroll
    for (int nt = 0; nt < 8; nt++) {
        int col = cb + nt * 8;
        float a1x = av[col], a1y = av[col + 1];
        float a2x = av[128 + col], a2y = av[128 + col + 1];
        float d0 = d[nt][0], d1 = d[nt][1], d2 = d[nt][2], d3 = d[nt][3];
        Ws[rloc * 130 + col] = d0;
        Ws[rloc * 130 + col + 1] = d1;
        Ws[(rloc + 8) * 130 + col] = d2;
        Ws[(rloc + 8) * 130 + col + 1] = d3;
        s1a += d0 * a1x + d1 * a1y;
        s2a += d0 * a2x + d1 * a2y;
        s1b += d2 * a1x + d3 * a1y;
        s2b += d2 * a2x + d3 * a2y;
    }
#pragma unroll
    for (int o = 1; o <= 2; o <<= 1) {
        s1a += __shfl_xor_sync(0xffffffffu, s1a, o);
        s2a += __shfl_xor_sync(0xffffffffu, s2a, o);
        s1b += __shfl_xor_sync(0xffffffffu, s1b, o);
        s2b += __shfl_xor_sync(0xffffffffu, s2b, o);
    }
    if ((lane & 3) == 0) {
        fr[(0 * 2 + wc) * 64 + rloc] = s1a;
        fr[(0 * 2 + wc) * 64 + rloc + 8] = s1b;
        fr[(1 * 2 + wc) * 64 + rloc] = s2a;
        fr[(1 * 2 + wc) * 64 + rloc + 8] = s2b;
    }
    __syncthreads();
    if (t < 64) {
        float v1 = fr[0 * 64 + t] + fr[1 * 64 + t];
        float v2 = fr[2 * 64 + t] + fr[3 * 64 + t];
        int idx = h * NN + row0 + t;
        f1g[idx] = v1;
        colB[idx] = __expf(v2);
        colD[idx] = __expf(0.2f * v2);
        float mm = v2;
#pragma unroll
        for (int o = 16; o; o >>= 1) mm = fmaxf(mm, __shfl_xor_sync(0xffffffffu, mm, o));
        if (lane == 0) sc[wid] = mm;
    }

    // transposed fp16 write (reads Ws; disjoint from fr/sc)
#pragma unroll
    for (int i = 0; i < 4; i++) {
        int n = t >> 1, kg = 4 * (t & 1) + i;
        __half hv[8];
#pragma unroll
        for (int j = 0; j < 8; j++)
            hv[j] = __float2half_rn(Ws[(kg * 8 + j) * 130 + n]);
        size_t o = (size_t)(h * 128 + n) * NN + row0 + kg * 8;
        *(uint4*)&WhT[o] = *(uint4*)hv;
    }
    __syncthreads();
    if (t == 0) fmaxp[h * 64 + blockIdx.x] = fmaxf(sc[0], sc[1]);
}

// ===========================================================================
// Pipelined mma.sync attention, single-pass fp16, 64-k chunks (R14 config).
// Loop order: stage(c+1) -> mma(c) -> pgen(c+1).
// CTA 64m x 128n, grid (64, H). smem (144B rows):
//   P[buf]: buf*9216 (64 x 144B); B[buf]: 18432 + buf*18432 (128 x 144B);
//   rowsum: 55296 (64 floats)
// ===========================================================================
#define ATT_SMEM 55552

__global__ void __launch_bounds__(256, 2)
attn_mma_kernel(const __half* __restrict__ WhT,
                const float* __restrict__ f1v, const float* __restrict__ fmaxp,
                const float* __restrict__ colB, const float* __restrict__ colD,
                const unsigned* __restrict__ mask,
                float* __restrict__ out, int out_stride,
                __nv_bfloat16* __restrict__ xhi, __nv_bfloat16* __restrict__ xlo) {
    extern __shared__ __align__(16) char smem[];
    uint32_t sb = smem_u32(smem);
    const uint32_t sP = sb;
    const uint32_t sB = sb + 18432;
    float* rsum = (float*)(smem + 55296);

    int h = blockIdx.y;
    int row0 = blockIdx.x * 64;
    int hbase = h * NN;
    int t = threadIdx.x, wid = t >> 5, lane = t & 31;
    int wr = wid & 3, wc = wid >> 2;

    const __half* Whh = WhT + (size_t)(h * 128) * NN;

    // per-head f2 max from 64 partials (all warps redundantly)
    float mF2 = fmaxf(fmaxp[h * 64 + lane], fmaxp[h * 64 + 32 + lane]);
#pragma unroll
    for (int o = 16; o; o >>= 1) mF2 = fmaxf(mF2, __shfl_xor_sync(0xffffffffu, mF2, o));

    // P-gen role: thread covers row pr (0..63), two k-octets kq0, kq0+1
    int pr = t >> 2, kq0 = (t & 3) * 2;
    float f1r = f1v[hbase + row0 + pr];
    float xm = f1r + mF2;
    float m = xm > 0.f ? xm : 0.2f * xm;
    float Ar = __expf(f1r - m);
    float Cr = __expf(0.2f * f1r - m);
    float psum = 0.f;

    const unsigned* mrow = mask + (size_t)(row0 + pr) * 128;
    const float* cBp = colB + hbase;
    const float* cDp = colD + hbase;

    uint32_t a_off = (uint32_t)(wr * 16 + ((lane >> 3) & 1) * 8 + (lane & 7)) * (PSTR2 * 2)
                   + (uint32_t)((lane >> 4) * 8) * 2;
    uint32_t b_roff = (uint32_t)(wc * 64 + (lane >> 4) * 8 + (lane & 7)) * (PSTR2 * 2);
    uint32_t b_koff = (uint32_t)(((lane >> 3) & 1) * 8) * 2;

    float d[8][4] = {};

    auto stage = [&](int c, int buf) {
#pragma unroll
        for (int l = 0; l < 4; l++) {
            int idx = t + l * 256;
            int n = idx >> 3, q = idx & 7;
            size_t go = (size_t)n * NN + c * 64 + q * 8;
            cp16(sB + (uint32_t)buf * 18432 + n * 144 + q * 16, Whh + go);
        }
        CP_COMMIT();
    };
    auto pgen = [&](int c, int buf) {
        unsigned wrd = mrow[2 * c + (kq0 >> 2)];
#pragma unroll
        for (int j2 = 0; j2 < 2; j2++) {
            int o = kq0 + j2;
            int kb = c * 64 + o * 8;
            unsigned w8 = wrd >> ((o & 3) * 8);
            float4 b0 = *(const float4*)(cBp + kb);
            float4 b1 = *(const float4*)(cBp + kb + 4);
            float4 d0 = *(const float4*)(cDp + kb);
            float4 d1 = *(const float4*)(cDp + kb + 4);
            float p[8];
            p[0] = (w8 & 1u)   ? fmaxf(Ar * b0.x, Cr * d0.x) : 0.f;
            p[1] = (w8 & 2u)   ? fmaxf(Ar * b0.y, Cr * d0.y) : 0.f;
            p[2] = (w8 & 4u)   ? fmaxf(Ar * b0.z, Cr * d0.z) : 0.f;
            p[3] = (w8 & 8u)   ? fmaxf(Ar * b0.w, Cr * d0.w) : 0.f;
            p[4] = (w8 & 16u)  ? fmaxf(Ar * b1.x, Cr * d1.x) : 0.f;
            p[5] = (w8 & 32u)  ? fmaxf(Ar * b1.y, Cr * d1.y) : 0.f;
            p[6] = (w8 & 64u)  ? fmaxf(Ar * b1.z, Cr * d1.z) : 0.f;
            p[7] = (w8 & 128u) ? fmaxf(Ar * b1.w, Cr * d1.w) : 0.f;
            psum += ((p[0] + p[1]) + (p[2] + p[3])) + ((p[4] + p[5]) + (p[6] + p[7]));
            uint4 u;
            unsigned* ph = &u.x;
#pragma unroll
            for (int j = 0; j < 4; j++) {
                __half2 h2 = __floats2half2_rn(p[2 * j], p[2 * j + 1]);
                ph[j] = *(unsigned*)&h2;
            }
            *(uint4*)(smem + buf * 9216 + pr * 144 + o * 16) = u;
        }
    };

    stage(0, 0);
    pgen(0, 0);

    for (int c = 0; c < 64; c++) {
        int buf = c & 1;
        CP_WAIT0();
        __syncthreads();     // publish B(c), P(c); readers of buf^1 done
        if (c + 1 < 64) stage(c + 1, buf ^ 1);   // cp.async overlaps mma below
        uint32_t pH = sP + (uint32_t)buf * 9216;
        uint32_t bH = sB + (uint32_t)buf * 18432;
#pragma unroll
        for (int s = 0; s < 4; s++) {
            unsigned ah[4];
            ldsm_x4(ah, pH + a_off + s * 32);
#pragma unroll
            for (int pp = 0; pp < 4; pp++) {
                unsigned bh[4];
                uint32_t boff = b_roff + (uint32_t)(pp * 16) * (PSTR2 * 2) + b_koff + s * 32;
                ldsm_x4(bh, bH + boff);
                mma_f16(d[2 * pp],     ah, bh);
                mma_f16(d[2 * pp + 1], ah, bh + 2);
            }
        }
        if (c + 1 < 64) pgen(c + 1, buf ^ 1);    // fills tensor-pipe drain window
    }

    psum += __shfl_xor_sync(0xffffffffu, psum, 1);
    psum += __shfl_xor_sync(0xffffffffu, psum, 2);
    if ((t & 3) == 0) rsum[pr] = psum;
    __syncthreads();

    int rloc = wr * 16 + (lane >> 2);
    float inv0 = 1.f / rsum[rloc];
    float inv1 = 1.f / rsum[rloc + 8];
    int r0 = row0 + rloc;
    int cbase = h * 128 + wc * 64 + (lane & 3) * 2;
#pragma unroll
    for (int nt = 0; nt < 8; nt++) {
        int col = cbase + nt * 8;
        float v0 = d[nt][0] * inv0, v1 = d[nt][1] * inv0;
        float v2 = d[nt][2] * inv1, v3 = d[nt][3] * inv1;
        v0 = v0 > 0.f ? v0 : expm1f(v0);
        v1 = v1 > 0.f ? v1 : expm1f(v1);
        v2 = v2 > 0.f ? v2 : expm1f(v2);
        v3 = v3 > 0.f ? v3 : expm1f(v3);
        if (xhi) {
            __nv_bfloat16 h0 = __float2bfloat16(v0), h1 = __float2bfloat16(v1);
            __nv_bfloat16 h2 = __float2bfloat16(v2), h3 = __float2bfloat16(v3);
            __nv_bfloat16 l0 = __float2bfloat16(v0 - __bfloat162float(h0));
            __nv_bfloat16 l1 = __float2bfloat16(v1 - __bfloat162float(h1));
            __nv_bfloat16 l2 = __float2bfloat16(v2 - __bfloat162float(h2));
            __nv_bfloat16 l3 = __float2bfloat16(v3 - __bfloat162float(h3));
            *(__nv_bfloat162*)&xhi[(size_t)r0 * 512 + col] = __nv_bfloat162(h0, h1);
            *(__nv_bfloat162*)&xlo[(size_t)r0 * 512 + col] = __nv_bfloat162(l0, l1);
            *(__nv_bfloat162*)&xhi[(size_t)(r0 + 8) * 512 + col] = __nv_bfloat162(h2, h3);
            *(__nv_bfloat162*)&xlo[(size_t)(r0 + 8) * 512 + col] = __nv_bfloat162(l2, l3);
        } else {
            *(float2*)&out[(size_t)r0 * out_stride + col] = make_float2(v0, v1);
            *(float2*)&out[(size_t)(r0 + 8) * out_stride + col] = make_float2(v2, v3);
        }
    }
}

// ===========================================================================
extern "C" void kernel_launch(void* const* d_in, const int* in_sizes, int n_in,
                              void* d_out, int out_size) {
    const int* head = (const int*)d_in[0];
    const int* rel = (const int*)d_in[1];
    const float* adj = (const float*)d_in[2];
    const float* ee = (const float*)d_in[3];
    const float* re = (const float*)d_in[4];
    const float* W0 = (const float*)d_in[5];
    const float* a0 = (const float*)d_in[6];
    const float* Wm = (const float*)d_in[7];
    const float* am = (const float*)d_in[8];
    const float* Wo = (const float*)d_in[9];
    const float* ao = (const float*)d_in[10];
    float* out = (float*)d_out;

    float *f1, *fmaxp, *cB, *cD;
    __half* WhT;
    __nv_bfloat16 *Xhi, *Xlo, *Wth, *Wtl;
    unsigned* mask;
    cudaGetSymbolAddress((void**)&f1, g_f1);
    cudaGetSymbolAddress((void**)&fmaxp, g_fmaxp);
    cudaGetSymbolAddress((void**)&cB, g_colB);
    cudaGetSymbolAddress((void**)&cD, g_colD);
    cudaGetSymbolAddress((void**)&WhT, g_WhT);
    cudaGetSymbolAddress((void**)&Xhi, g_Xhi);
    cudaGetSymbolAddress((void**)&Xlo, g_Xlo);
    cudaGetSymbolAddress((void**)&Wth, g_Wt_hi);
    cudaGetSymbolAddress((void**)&Wtl, g_Wt_lo);
    cudaGetSymbolAddress((void**)&mask, g_mask);

    cudaFuncSetAttribute(attn_mma_kernel, cudaFuncAttributeMaxDynamicSharedMemorySize, ATT_SMEM);
    cudaFuncSetAttribute(gemm_fused_kernel, cudaFuncAttributeMaxDynamicSharedMemorySize, GEMM_SMEM);

    build_mask_kernel<<<NN, 256>>>(adj, mask);
    hrc_kernel<<<NN, 128>>>(head, rel, ee, re, out + (size_t)NN * 128);
    split_kernel<<<(NN * 128 + 255) / 256, 256>>>(ee, Xhi, Xlo, NN * 128);
    wsplit_all_kernel<<<2432, 256>>>(W0, Wm, Wo, Wth, Wtl);

    // ---- layer 0: Fin = 128 ----
    gemm_fused_kernel<<<dim3(64, HH), 256, GEMM_SMEM>>>(Xhi, Xlo, Wth + WT_OFF0, Wtl + WT_OFF0,
                                                        a0, WhT, f1, cB, cD, fmaxp, 128);
    attn_mma_kernel<<<dim3(64, HH), 256, ATT_SMEM>>>(WhT, f1, fmaxp, cB, cD, mask,
                                                     nullptr, 0, Xhi, Xlo);

    // ---- 9 middle layers: Fin = 512 ----
    for (int l = 0; l < NMID; l++) {
        gemm_fused_kernel<<<dim3(64, HH), 256, GEMM_SMEM>>>(Xhi, Xlo,
                                                            Wth + WT_OFFM(l), Wtl + WT_OFFM(l),
                                                            am + (size_t)l * HH * 256,
                                                            WhT, f1, cB, cD, fmaxp, 512);
        attn_mma_kernel<<<dim3(64, HH), 256, ATT_SMEM>>>(WhT, f1, fmaxp, cB, cD, mask,
                                                         nullptr, 0, Xhi, Xlo);
    }

    // ---- output layer: 1 head, Fin = 512 ----
    gemm_fused_kernel<<<dim3(64, 1), 256, GEMM_SMEM>>>(Xhi, Xlo, Wth + WT_OFFO, Wtl + WT_OFFO,
                                                       ao, WhT, f1, cB, cD, fmaxp, 512);
    attn_mma_kernel<<<dim3(64, 1), 256, ATT_SMEM>>>(WhT, f1, fmaxp, cB, cD, mask,
                                                    out, 128, nullptr, nullptr);
}